// round 1
// baseline (speedup 1.0000x reference)
#include <cuda_runtime.h>
#include <cuda_bf16.h>
#include <math.h>

#define NHEADS 4
#define HD 64
#define NQ 256
#define NK 257
#define KDIM 128
#define ROWP 65   // padded smem row stride (floats) -> conflict-free

__device__ float g_maxpool[32 * NHEADS * HD];   // scratch: (B, H, 64)

__device__ __forceinline__ float gelu_exact(float x) {
    // jax.nn.gelu(approximate=False) = 0.5*x*(1+erf(x/sqrt(2)))
    return 0.5f * x * (1.0f + erff(x * 0.70710678118654752440f));
}

// ---------------------------------------------------------------------------
// Kernel 1: fused projections + attention + combine + max-pool, one (b,h)/block
// ---------------------------------------------------------------------------
extern __shared__ float smem[];

__global__ __launch_bounds__(256, 1)
void attn_fused_kernel(
    const float* __restrict__ seq,     // (32, 4096, 768)
    const float* __restrict__ node1,   // (32, 128, 256)
    const float* __restrict__ node2,   // (32, 128, 256)
    const float* __restrict__ Wq, const float* __restrict__ bq,
    const float* __restrict__ Wk, const float* __restrict__ bk,
    const float* __restrict__ Wv, const float* __restrict__ bv)
{
    const int h = blockIdx.x;
    const int b = blockIdx.y;
    const int t = threadIdx.x;

    float* sW   = smem;                 // 128*64
    float* sK2  = sW  + KDIM * HD;      // 257*65
    float* sGV2 = sK2 + NK * ROWP;      // 257*65

    const float* n1b    = node1 + (size_t)b * KDIM * 256;
    const float* n2b    = node2 + (size_t)b * KDIM * 256;
    const float* pooled = seq   + (size_t)b * 4096 * 768;  // row 0 of seq

    // ======== Phase V2: gelu(v2) -> sGV2 (257 rows) ========
    for (int i = t; i < KDIM * HD; i += 256)
        sW[i] = Wv[(i >> 6) * 256 + h * HD + (i & 63)];
    __syncthreads();
    {
        float acc[HD];
        #pragma unroll
        for (int o = 0; o < HD; o++) acc[o] = bv[h * HD + o];
        for (int k = 0; k < KDIM; k++) {
            float xv = n2b[k * 256 + t];
            const float* w = &sW[k * HD];
            #pragma unroll
            for (int o = 0; o < HD; o++) acc[o] = fmaf(xv, w[o], acc[o]);
        }
        #pragma unroll
        for (int o = 0; o < HD; o++) sGV2[t * ROWP + o] = gelu_exact(acc[o]);
        if (t < HD) {  // row 256 = pooled[:128]
            float a = bv[h * HD + t];
            for (int k = 0; k < KDIM; k++) a = fmaf(pooled[k], sW[k * HD + t], a);
            sGV2[256 * ROWP + t] = gelu_exact(a);
        }
    }
    __syncthreads();

    // ======== Phase K2 -> sK2 (257 rows) ========
    for (int i = t; i < KDIM * HD; i += 256)
        sW[i] = Wk[(i >> 6) * 256 + h * HD + (i & 63)];
    __syncthreads();
    {
        float acc[HD];
        #pragma unroll
        for (int o = 0; o < HD; o++) acc[o] = bk[h * HD + o];
        for (int k = 0; k < KDIM; k++) {
            float xv = n2b[k * 256 + t];
            const float* w = &sW[k * HD];
            #pragma unroll
            for (int o = 0; o < HD; o++) acc[o] = fmaf(xv, w[o], acc[o]);
        }
        #pragma unroll
        for (int o = 0; o < HD; o++) sK2[t * ROWP + o] = acc[o];
        if (t < HD) {
            float a = bk[h * HD + t];
            for (int k = 0; k < KDIM; k++) a = fmaf(pooled[k], sW[k * HD + t], a);
            sK2[256 * ROWP + t] = a;
        }
    }
    __syncthreads();

    // ======== Phase Q (kept in registers) ========
    for (int i = t; i < KDIM * HD; i += 256)
        sW[i] = Wq[(i >> 6) * 256 + h * HD + (i & 63)];
    __syncthreads();
    float q[HD];
    #pragma unroll
    for (int o = 0; o < HD; o++) q[o] = bq[h * HD + o];
    for (int k = 0; k < KDIM; k++) {
        float xv = n1b[k * 256 + t];
        const float* w = &sW[k * HD];
        #pragma unroll
        for (int o = 0; o < HD; o++) q[o] = fmaf(xv, w[o], q[o]);
    }

    // ======== Attention: online softmax over 257 keys (thread = query row) ====
    float ctx[HD];
    float m, l;
    {   // j = 0
        const float* kj = &sK2[0];
        float s = 0.f;
        #pragma unroll
        for (int o = 0; o < HD; o++) s = fmaf(q[o], kj[o], s);
        m = s * 0.125f;
        l = 1.f;
        const float* vj = &sGV2[0];
        #pragma unroll
        for (int o = 0; o < HD; o++) ctx[o] = vj[o];
    }
    for (int j = 1; j < NK; j++) {
        const float* kj = &sK2[j * ROWP];
        float s = 0.f;
        #pragma unroll
        for (int o = 0; o < HD; o++) s = fmaf(q[o], kj[o], s);
        s *= 0.125f;
        const float* vj = &sGV2[j * ROWP];
        if (s <= m) {
            float p = __expf(s - m);
            l += p;
            #pragma unroll
            for (int o = 0; o < HD; o++) ctx[o] = fmaf(p, vj[o], ctx[o]);
        } else {   // rare: new max, rescale
            float c = __expf(m - s);
            l = fmaf(l, c, 1.f);
            #pragma unroll
            for (int o = 0; o < HD; o++) ctx[o] = fmaf(ctx[o], c, vj[o]);
            m = s;
        }
    }
    const float inv_l = 1.f / l;

    // ======== Recompute gelu(v1), combine, write rows into sK2 (reuse) =======
    __syncthreads();   // everyone done reading sK2/sGV2/sW
    for (int i = t; i < KDIM * HD; i += 256)
        sW[i] = Wv[(i >> 6) * 256 + h * HD + (i & 63)];
    __syncthreads();
    {
        float acc[HD];
        #pragma unroll
        for (int o = 0; o < HD; o++) acc[o] = bv[h * HD + o];
        for (int k = 0; k < KDIM; k++) {
            float xv = n1b[k * 256 + t];
            const float* w = &sW[k * HD];
            #pragma unroll
            for (int o = 0; o < HD; o++) acc[o] = fmaf(xv, w[o], acc[o]);
        }
        #pragma unroll
        for (int o = 0; o < HD; o++)
            sK2[t * ROWP + o] = fmaf(ctx[o], inv_l, gelu_exact(acc[o]));
    }
    __syncthreads();

    // ======== Max over 256 query rows -> g_maxpool[b,h,:] ========
    if (t < HD) {
        float mx = -1e30f;
        for (int n = 0; n < NQ; n++) mx = fmaxf(mx, sK2[n * ROWP + t]);
        g_maxpool[(b * NHEADS + h) * HD + t] = mx;
    }
}

// ---------------------------------------------------------------------------
// Kernel 2: Wo proj + layernorm + fc1/fc2/fc3, one batch/block
// ---------------------------------------------------------------------------
__device__ __forceinline__ float block_sum(float v, float* red, int t) {
    __syncthreads();            // protect red from previous use
    #pragma unroll
    for (int off = 16; off; off >>= 1) v += __shfl_xor_sync(0xffffffffu, v, off);
    if ((t & 31) == 0) red[t >> 5] = v;
    __syncthreads();
    if (t < 8) {
        v = red[t];
        #pragma unroll
        for (int off = 4; off; off >>= 1) v += __shfl_xor_sync(0xffu, v, off);
        if (t == 0) red[0] = v;
    }
    __syncthreads();
    return red[0];
}

__global__ __launch_bounds__(256)
void head_kernel(
    const float* __restrict__ seq,
    const float* __restrict__ Wo,    const float* __restrict__ bo,
    const float* __restrict__ ln_g,  const float* __restrict__ ln_b,
    const float* __restrict__ fc1_w, const float* __restrict__ fc1_b,
    const float* __restrict__ fc2_w, const float* __restrict__ fc2_b,
    const float* __restrict__ fc3_w, const float* __restrict__ fc3_b,
    float* __restrict__ out)
{
    __shared__ float emb[832];
    __shared__ float h1[512];
    __shared__ float h2[200];
    __shared__ float red[32];

    const int b = blockIdx.x;
    const int t = threadIdx.x;
    const float* mp = &g_maxpool[b * 256];

    // emb[0:768] = pooled ; emb[768:832] = max_pooled @ Wo + bo
    for (int i = t; i < 768; i += 256)
        emb[i] = seq[(size_t)b * 4096 * 768 + i];
    if (t < 64) {
        float a = bo[t];
        for (int k = 0; k < 256; k++) a = fmaf(mp[k], Wo[k * 64 + t], a);
        emb[768 + t] = a;
    }
    __syncthreads();

    // layernorm (two-pass, biased var)
    float s = 0.f;
    for (int i = t; i < 832; i += 256) s += emb[i];
    float mu = block_sum(s, red, t) * (1.0f / 832.0f);
    float vs = 0.f;
    for (int i = t; i < 832; i += 256) { float d = emb[i] - mu; vs += d * d; }
    float var = block_sum(vs, red, t) * (1.0f / 832.0f);
    float inv_std = rsqrtf(var + 1e-5f);
    for (int i = t; i < 832; i += 256)
        emb[i] = (emb[i] - mu) * inv_std * ln_g[i] + ln_b[i];
    __syncthreads();

    // fc1: 832 -> 512, gelu
    {
        float a0 = fc1_b[t], a1 = fc1_b[t + 256];
        for (int k = 0; k < 832; k++) {
            float e = emb[k];
            a0 = fmaf(e, fc1_w[k * 512 + t],       a0);
            a1 = fmaf(e, fc1_w[k * 512 + t + 256], a1);
        }
        h1[t]       = gelu_exact(a0);
        h1[t + 256] = gelu_exact(a1);
    }
    __syncthreads();

    // fc2: 512 -> 200, gelu
    if (t < 200) {
        float a = fc2_b[t];
        for (int k = 0; k < 512; k++) a = fmaf(h1[k], fc2_w[k * 200 + t], a);
        h2[t] = gelu_exact(a);
    }
    __syncthreads();

    // fc3: 200 -> 2
    if (t < 2) {
        float a = fc3_b[t];
        for (int k = 0; k < 200; k++) a = fmaf(h2[k], fc3_w[k * 2 + t], a);
        out[b * 2 + t] = a;
    }
}

// ---------------------------------------------------------------------------
extern "C" void kernel_launch(void* const* d_in, const int* in_sizes, int n_in,
                              void* d_out, int out_size)
{
    const float* seq    = (const float*)d_in[0];
    const float* node1  = (const float*)d_in[1];
    const float* node2  = (const float*)d_in[2];
    const float* Wq     = (const float*)d_in[3];
    const float* bq     = (const float*)d_in[4];
    const float* Wk     = (const float*)d_in[5];
    const float* bk     = (const float*)d_in[6];
    const float* Wv     = (const float*)d_in[7];
    const float* bv     = (const float*)d_in[8];
    const float* Wo     = (const float*)d_in[9];
    const float* bo     = (const float*)d_in[10];
    const float* ln_g   = (const float*)d_in[11];
    const float* ln_b   = (const float*)d_in[12];
    const float* fc1_w  = (const float*)d_in[13];
    const float* fc1_b  = (const float*)d_in[14];
    const float* fc2_w  = (const float*)d_in[15];
    const float* fc2_b  = (const float*)d_in[16];
    const float* fc3_w  = (const float*)d_in[17];
    const float* fc3_b  = (const float*)d_in[18];

    const size_t smem_bytes = (size_t)(KDIM * HD + 2 * NK * ROWP) * sizeof(float);
    cudaFuncSetAttribute(attn_fused_kernel,
                         cudaFuncAttributeMaxDynamicSharedMemorySize,
                         (int)smem_bytes);

    attn_fused_kernel<<<dim3(NHEADS, 32), 256, smem_bytes>>>(
        seq, node1, node2, Wq, bq, Wk, bk, Wv, bv);

    head_kernel<<<32, 256>>>(
        seq, Wo, bo, ln_g, ln_b, fc1_w, fc1_b, fc2_w, fc2_b, fc3_w, fc3_b,
        (float*)d_out);
}

// round 2
// speedup vs baseline: 1.4356x; 1.4356x over previous
#include <cuda_runtime.h>
#include <cuda_bf16.h>
#include <math.h>

#define NHEADS 4
#define HD 64
#define NQ 256
#define NK 257
#define KDIM 128
#define ROWP 68   // padded smem row stride (floats): 16B-aligned rows, conflict-free f4 stores

typedef unsigned long long ull;

__device__ float g_maxpool[32 * NHEADS * HD];   // scratch: (B, H, 64)

__device__ __forceinline__ float gelu_exact(float x) {
    return 0.5f * x * (1.0f + erff(x * 0.70710678118654752440f));
}

// ---- packed f32x2 helpers (SASS FFMA2) ----
__device__ __forceinline__ ull ffma2(ull a, ull b, ull c) {
    ull d; asm("fma.rn.f32x2 %0, %1, %2, %3;" : "=l"(d) : "l"(a), "l"(b), "l"(c)); return d;
}
__device__ __forceinline__ ull mul2(ull a, ull b) {
    ull d; asm("mul.rn.f32x2 %0, %1, %2;" : "=l"(d) : "l"(a), "l"(b)); return d;
}
__device__ __forceinline__ ull pack2(float lo, float hi) {
    ull d; asm("mov.b64 %0, {%1, %2};" : "=l"(d) : "f"(lo), "f"(hi)); return d;
}
__device__ __forceinline__ float2 unpack2(ull a) {
    float lo, hi; asm("mov.b64 {%0, %1}, %2;" : "=f"(lo), "=f"(hi) : "l"(a));
    return make_float2(lo, hi);
}

// one projection row: acc2[32] (64 outputs packed) = x_row @ sW + bias
__device__ __forceinline__ void proj_row(
    const float* __restrict__ x, const float* sW,
    const float* __restrict__ bias, int t, ull acc2[32])
{
    const float2* b2 = (const float2*)bias;
    #pragma unroll
    for (int i = 0; i < 32; i++) { float2 b = b2[i]; acc2[i] = pack2(b.x, b.y); }
    #pragma unroll 2
    for (int k = 0; k < KDIM; k++) {
        float xv = x[k * 256 + t];
        ull xv2 = pack2(xv, xv);
        const ulonglong2* w2 = (const ulonglong2*)&sW[k * HD];
        #pragma unroll
        for (int i = 0; i < 16; i++) {
            ulonglong2 w = w2[i];
            acc2[2*i]   = ffma2(xv2, w.x, acc2[2*i]);
            acc2[2*i+1] = ffma2(xv2, w.y, acc2[2*i+1]);
        }
    }
}

// ---------------------------------------------------------------------------
// Kernel 1: fused projections + attention + combine + max-pool, one (b,h)/block
// ---------------------------------------------------------------------------
extern __shared__ float smem[];

__global__ __launch_bounds__(256, 1)
void attn_fused_kernel(
    const float* __restrict__ seq,     // (32, 4096, 768)
    const float* __restrict__ node1,   // (32, 128, 256)
    const float* __restrict__ node2,   // (32, 128, 256)
    const float* __restrict__ Wq, const float* __restrict__ bq,
    const float* __restrict__ Wk, const float* __restrict__ bk,
    const float* __restrict__ Wv, const float* __restrict__ bv)
{
    const int h = blockIdx.x;
    const int b = blockIdx.y;
    const int t = threadIdx.x;

    float* sW   = smem;                 // 128*64
    float* sK2  = sW  + KDIM * HD;      // 257*68
    float* sGV2 = sK2 + NK * ROWP;      // 257*68

    const float* n1b    = node1 + (size_t)b * KDIM * 256;
    const float* n2b    = node2 + (size_t)b * KDIM * 256;
    const float* pooled = seq   + (size_t)b * 4096 * 768;  // row 0

    // ======== Phase V2: gelu(v2) -> sGV2 (257 rows) ========
    for (int i = t; i < KDIM * HD; i += 256)
        sW[i] = Wv[(i >> 6) * 256 + h * HD + (i & 63)];
    __syncthreads();
    {
        ull acc2[32];
        proj_row(n2b, sW, bv + h * HD, t, acc2);
        float4* dst = (float4*)&sGV2[t * ROWP];
        #pragma unroll
        for (int i = 0; i < 16; i++) {
            float2 a0 = unpack2(acc2[2*i]), a1 = unpack2(acc2[2*i+1]);
            float4 r;
            r.x = gelu_exact(a0.x); r.y = gelu_exact(a0.y);
            r.z = gelu_exact(a1.x); r.w = gelu_exact(a1.y);
            dst[i] = r;
        }
        if (t < HD) {   // row 256 = pooled[:128]
            float a = bv[h * HD + t];
            #pragma unroll 4
            for (int k = 0; k < KDIM; k++) a = fmaf(pooled[k], sW[k * HD + t], a);
            sGV2[256 * ROWP + t] = gelu_exact(a);
        }
    }
    __syncthreads();

    // ======== Phase K2 -> sK2 (257 rows) ========
    for (int i = t; i < KDIM * HD; i += 256)
        sW[i] = Wk[(i >> 6) * 256 + h * HD + (i & 63)];
    __syncthreads();
    {
        ull acc2[32];
        proj_row(n2b, sW, bk + h * HD, t, acc2);
        float4* dst = (float4*)&sK2[t * ROWP];
        #pragma unroll
        for (int i = 0; i < 16; i++) {
            float2 a0 = unpack2(acc2[2*i]), a1 = unpack2(acc2[2*i+1]);
            dst[i] = make_float4(a0.x, a0.y, a1.x, a1.y);
        }
        if (t < HD) {
            float a = bk[h * HD + t];
            #pragma unroll 4
            for (int k = 0; k < KDIM; k++) a = fmaf(pooled[k], sW[k * HD + t], a);
            sK2[256 * ROWP + t] = a;
        }
    }
    __syncthreads();

    // ======== Phase Q (registers, pre-scaled by 1/8) ========
    for (int i = t; i < KDIM * HD; i += 256)
        sW[i] = Wq[(i >> 6) * 256 + h * HD + (i & 63)];
    __syncthreads();
    ull q2[32];
    proj_row(n1b, sW, bq + h * HD, t, q2);
    {
        ull sc = pack2(0.125f, 0.125f);
        #pragma unroll
        for (int i = 0; i < 32; i++) q2[i] = mul2(q2[i], sc);
    }

    // ======== Attention: online softmax over 257 keys (thread = query row) ====
    ull ctx2[32];
    float m, l;
    {   // j = 0
        const ulonglong2* kr = (const ulonglong2*)&sK2[0];
        ull sa = pack2(0.f, 0.f), sb = sa, sc_ = sa, sd = sa;
        #pragma unroll
        for (int i = 0; i < 8; i++) {
            ulonglong2 ka = kr[2*i], kb = kr[2*i+1];
            sa = ffma2(q2[4*i],   ka.x, sa);
            sb = ffma2(q2[4*i+1], ka.y, sb);
            sc_ = ffma2(q2[4*i+2], kb.x, sc_);
            sd = ffma2(q2[4*i+3], kb.y, sd);
        }
        float2 fa = unpack2(sa), fb = unpack2(sb), fc_ = unpack2(sc_), fd = unpack2(sd);
        m = ((fa.x + fa.y) + (fb.x + fb.y)) + ((fc_.x + fc_.y) + (fd.x + fd.y));
        l = 1.f;
        const ulonglong2* vr = (const ulonglong2*)&sGV2[0];
        #pragma unroll
        for (int i = 0; i < 16; i++) { ulonglong2 v = vr[i]; ctx2[2*i] = v.x; ctx2[2*i+1] = v.y; }
    }
    for (int j = 1; j < NK; j++) {
        const ulonglong2* kr = (const ulonglong2*)&sK2[j * ROWP];
        ull sa = pack2(0.f, 0.f), sb = sa, sc_ = sa, sd = sa;
        #pragma unroll
        for (int i = 0; i < 8; i++) {
            ulonglong2 ka = kr[2*i], kb = kr[2*i+1];
            sa = ffma2(q2[4*i],   ka.x, sa);
            sb = ffma2(q2[4*i+1], ka.y, sb);
            sc_ = ffma2(q2[4*i+2], kb.x, sc_);
            sd = ffma2(q2[4*i+3], kb.y, sd);
        }
        float2 fa = unpack2(sa), fb = unpack2(sb), fc_ = unpack2(sc_), fd = unpack2(sd);
        float s = ((fa.x + fa.y) + (fb.x + fb.y)) + ((fc_.x + fc_.y) + (fd.x + fd.y));
        const ulonglong2* vr = (const ulonglong2*)&sGV2[j * ROWP];
        if (s <= m) {
            float p = __expf(s - m);
            l += p;
            ull p2 = pack2(p, p);
            #pragma unroll
            for (int i = 0; i < 16; i++) {
                ulonglong2 v = vr[i];
                ctx2[2*i]   = ffma2(p2, v.x, ctx2[2*i]);
                ctx2[2*i+1] = ffma2(p2, v.y, ctx2[2*i+1]);
            }
        } else {   // rare: new max, rescale
            float c = __expf(m - s);
            l = fmaf(l, c, 1.f);
            ull c2 = pack2(c, c);
            #pragma unroll
            for (int i = 0; i < 16; i++) {
                ulonglong2 v = vr[i];
                ctx2[2*i]   = ffma2(ctx2[2*i],   c2, v.x);
                ctx2[2*i+1] = ffma2(ctx2[2*i+1], c2, v.y);
            }
            m = s;
        }
    }
    const float inv_l = 1.f / l;

    // ======== gelu(v1) + combine -> sK2 rows (reuse) ========
    __syncthreads();   // all threads done reading sW/sK2/sGV2
    for (int i = t; i < KDIM * HD; i += 256)
        sW[i] = Wv[(i >> 6) * 256 + h * HD + (i & 63)];
    __syncthreads();
    {
        ull acc2[32];
        proj_row(n1b, sW, bv + h * HD, t, acc2);
        float4* dst = (float4*)&sK2[t * ROWP];
        #pragma unroll
        for (int i = 0; i < 16; i++) {
            float2 a0 = unpack2(acc2[2*i]), a1 = unpack2(acc2[2*i+1]);
            float2 c0 = unpack2(ctx2[2*i]), c1 = unpack2(ctx2[2*i+1]);
            float4 r;
            r.x = fmaf(c0.x, inv_l, gelu_exact(a0.x));
            r.y = fmaf(c0.y, inv_l, gelu_exact(a0.y));
            r.z = fmaf(c1.x, inv_l, gelu_exact(a1.x));
            r.w = fmaf(c1.y, inv_l, gelu_exact(a1.y));
            dst[i] = r;
        }
    }
    __syncthreads();

    // ======== Max over 256 query rows -> g_maxpool[b,h,:] (4-way split) ======
    {
        int o = t & 63, seg = t >> 6;
        float mx = -1e30f;
        #pragma unroll 8
        for (int n = seg * 64; n < seg * 64 + 64; n++)
            mx = fmaxf(mx, sK2[n * ROWP + o]);
        sGV2[seg * 64 + o] = mx;   // reuse as scratch
    }
    __syncthreads();
    if (t < HD) {
        float mx = fmaxf(fmaxf(sGV2[t], sGV2[64 + t]),
                         fmaxf(sGV2[128 + t], sGV2[192 + t]));
        g_maxpool[(b * NHEADS + h) * HD + t] = mx;
    }
}

// ---------------------------------------------------------------------------
// Kernel 2: Wo proj + layernorm + fc1/fc2/fc3, one batch/block
// ---------------------------------------------------------------------------
__device__ __forceinline__ float block_sum(float v, float* red, int t) {
    __syncthreads();
    #pragma unroll
    for (int off = 16; off; off >>= 1) v += __shfl_xor_sync(0xffffffffu, v, off);
    if ((t & 31) == 0) red[t >> 5] = v;
    __syncthreads();
    if (t < 8) {
        v = red[t];
        #pragma unroll
        for (int off = 4; off; off >>= 1) v += __shfl_xor_sync(0xffu, v, off);
        if (t == 0) red[0] = v;
    }
    __syncthreads();
    return red[0];
}

__global__ __launch_bounds__(256)
void head_kernel(
    const float* __restrict__ seq,
    const float* __restrict__ Wo,    const float* __restrict__ bo,
    const float* __restrict__ ln_g,  const float* __restrict__ ln_b,
    const float* __restrict__ fc1_w, const float* __restrict__ fc1_b,
    const float* __restrict__ fc2_w, const float* __restrict__ fc2_b,
    const float* __restrict__ fc3_w, const float* __restrict__ fc3_b,
    float* __restrict__ out)
{
    __shared__ float mp_s[256];
    __shared__ float emb[832];
    __shared__ float h1[512];
    __shared__ float h2[200];
    __shared__ float red[32];
    __shared__ float wo_part[4][64];

    const int b = blockIdx.x;
    const int t = threadIdx.x;

    mp_s[t] = g_maxpool[b * 256 + t];
    for (int i = t; i < 768; i += 256)
        emb[i] = seq[(size_t)b * 4096 * 768 + i];
    __syncthreads();

    // Wo projection: 4-way K split over 256 threads
    {
        int o = t & 63, seg = t >> 6;
        float a = 0.f;
        #pragma unroll 8
        for (int k = seg * 64; k < seg * 64 + 64; k++)
            a = fmaf(mp_s[k], Wo[k * 64 + o], a);
        wo_part[seg][o] = a;
    }
    __syncthreads();
    if (t < 64)
        emb[768 + t] = wo_part[0][t] + wo_part[1][t] + wo_part[2][t] + wo_part[3][t] + bo[t];
    __syncthreads();

    // layernorm (two-pass, biased var)
    float s = 0.f;
    for (int i = t; i < 832; i += 256) s += emb[i];
    float mu = block_sum(s, red, t) * (1.0f / 832.0f);
    float vs = 0.f;
    for (int i = t; i < 832; i += 256) { float d = emb[i] - mu; vs += d * d; }
    float var = block_sum(vs, red, t) * (1.0f / 832.0f);
    float inv_std = rsqrtf(var + 1e-5f);
    for (int i = t; i < 832; i += 256)
        emb[i] = (emb[i] - mu) * inv_std * ln_g[i] + ln_b[i];
    __syncthreads();

    // fc1: 832 -> 512 (thread t owns outputs 2t, 2t+1; FFMA2 + float2 loads)
    {
        const float2* w2 = (const float2*)fc1_w;   // w2[k*256 + t]
        float2 bb = ((const float2*)fc1_b)[t];
        ull acc_a = pack2(bb.x, bb.y);
        ull acc_b = pack2(0.f, 0.f);
        #pragma unroll 8
        for (int k = 0; k < 832; k += 2) {
            float e0 = emb[k], e1 = emb[k + 1];
            float2 wa = w2[k * 256 + t];
            float2 wb = w2[(k + 1) * 256 + t];
            acc_a = ffma2(pack2(e0, e0), pack2(wa.x, wa.y), acc_a);
            acc_b = ffma2(pack2(e1, e1), pack2(wb.x, wb.y), acc_b);
        }
        float2 a = unpack2(acc_a), bq_ = unpack2(acc_b);
        h1[2*t]     = gelu_exact(a.x + bq_.x);
        h1[2*t + 1] = gelu_exact(a.y + bq_.y);
    }
    __syncthreads();

    // fc2: 512 -> 200, gelu (dual accumulators, unrolled)
    if (t < 200) {
        float a0 = fc2_b[t], a1 = 0.f;
        #pragma unroll 8
        for (int k = 0; k < 512; k += 2) {
            a0 = fmaf(h1[k],     fc2_w[k * 200 + t],       a0);
            a1 = fmaf(h1[k + 1], fc2_w[(k + 1) * 200 + t], a1);
        }
        h2[t] = gelu_exact(a0 + a1);
    }
    __syncthreads();

    // fc3: 200 -> 2 (warp 0 -> out0, warp 1 -> out1, lane-split K + shfl reduce)
    if (t < 64) {
        int o = t >> 5, lane = t & 31;
        float a = 0.f;
        #pragma unroll
        for (int k = lane; k < 200; k += 32) a = fmaf(h2[k], fc3_w[k * 2 + o], a);
        #pragma unroll
        for (int off = 16; off; off >>= 1) a += __shfl_xor_sync(0xffffffffu, a, off);
        if (lane == 0) out[b * 2 + o] = a + fc3_b[o];
    }
}

// ---------------------------------------------------------------------------
extern "C" void kernel_launch(void* const* d_in, const int* in_sizes, int n_in,
                              void* d_out, int out_size)
{
    const float* seq    = (const float*)d_in[0];
    const float* node1  = (const float*)d_in[1];
    const float* node2  = (const float*)d_in[2];
    const float* Wq     = (const float*)d_in[3];
    const float* bq     = (const float*)d_in[4];
    const float* Wk     = (const float*)d_in[5];
    const float* bk     = (const float*)d_in[6];
    const float* Wv     = (const float*)d_in[7];
    const float* bv     = (const float*)d_in[8];
    const float* Wo     = (const float*)d_in[9];
    const float* bo     = (const float*)d_in[10];
    const float* ln_g   = (const float*)d_in[11];
    const float* ln_b   = (const float*)d_in[12];
    const float* fc1_w  = (const float*)d_in[13];
    const float* fc1_b  = (const float*)d_in[14];
    const float* fc2_w  = (const float*)d_in[15];
    const float* fc2_b  = (const float*)d_in[16];
    const float* fc3_w  = (const float*)d_in[17];
    const float* fc3_b  = (const float*)d_in[18];

    const size_t smem_bytes = (size_t)(KDIM * HD + 2 * NK * ROWP) * sizeof(float);
    cudaFuncSetAttribute(attn_fused_kernel,
                         cudaFuncAttributeMaxDynamicSharedMemorySize,
                         (int)smem_bytes);

    attn_fused_kernel<<<dim3(NHEADS, 32), 256, smem_bytes>>>(
        seq, node1, node2, Wq, bq, Wk, bk, Wv, bv);

    head_kernel<<<32, 256>>>(
        seq, Wo, bo, ln_g, ln_b, fc1_w, fc1_b, fc2_w, fc2_b, fc3_w, fc3_b,
        (float*)d_out);
}

// round 3
// speedup vs baseline: 1.7530x; 1.2211x over previous
#include <cuda_runtime.h>
#include <cuda_bf16.h>
#include <math.h>

#define NHEADS 4
#define HD 64
#define NQ 256
#define NK 257
#define KDIM 128
#define ROWP 68   // padded smem row stride (floats): 16B-aligned rows, conflict-free

typedef unsigned long long ull;

__device__ float g_maxpool[32 * NHEADS * HD];       // (B,H,64)
__device__ float g_v1[32 * NHEADS * NQ * HD];       // gelu(v1): per (b,h): 256x64
__device__ float g_emb[32 * 832];                   // post-layernorm embedding
__device__ float g_h1[32 * 512];                    // gelu(fc1)
__device__ float g_h2p[2 * 32 * 200];               // fc2 partials (k-split 2)

__device__ __forceinline__ float gelu_exact(float x) {
    return 0.5f * x * (1.0f + erff(x * 0.70710678118654752440f));
}

// ---- packed f32x2 helpers (SASS FFMA2) ----
__device__ __forceinline__ ull ffma2(ull a, ull b, ull c) {
    ull d; asm("fma.rn.f32x2 %0, %1, %2, %3;" : "=l"(d) : "l"(a), "l"(b), "l"(c)); return d;
}
__device__ __forceinline__ ull mul2(ull a, ull b) {
    ull d; asm("mul.rn.f32x2 %0, %1, %2;" : "=l"(d) : "l"(a), "l"(b)); return d;
}
__device__ __forceinline__ ull pack2(float lo, float hi) {
    ull d; asm("mov.b64 %0, {%1, %2};" : "=l"(d) : "f"(lo), "f"(hi)); return d;
}
__device__ __forceinline__ float2 unpack2(ull a) {
    float lo, hi; asm("mov.b64 {%0, %1}, %2;" : "=f"(lo), "=f"(hi) : "l"(a));
    return make_float2(lo, hi);
}

// acc2[32] (64 packed outputs) = x_row @ sW + bias
__device__ __forceinline__ void proj_row(
    const float* __restrict__ x, const float* sW,
    const float* __restrict__ bias, int t, ull acc2[32])
{
    const float2* b2 = (const float2*)bias;
    #pragma unroll
    for (int i = 0; i < 32; i++) { float2 b = b2[i]; acc2[i] = pack2(b.x, b.y); }
    #pragma unroll 4
    for (int k = 0; k < KDIM; k++) {
        float xv = x[k * 256 + t];
        ull xv2 = pack2(xv, xv);
        const ulonglong2* w2 = (const ulonglong2*)&sW[k * HD];
        #pragma unroll
        for (int i = 0; i < 16; i++) {
            ulonglong2 w = w2[i];
            acc2[2*i]   = ffma2(xv2, w.x, acc2[2*i]);
            acc2[2*i+1] = ffma2(xv2, w.y, acc2[2*i+1]);
        }
    }
}

// ---------------------------------------------------------------------------
// Kernel 1: projections + attention + combine + max-pool, one (b,h) per block
// ---------------------------------------------------------------------------
extern __shared__ float smem[];

__global__ __launch_bounds__(256, 1)
void attn_fused_kernel(
    const float* __restrict__ seq,
    const float* __restrict__ node1,
    const float* __restrict__ node2,
    const float* __restrict__ Wq, const float* __restrict__ bq,
    const float* __restrict__ Wk, const float* __restrict__ bk,
    const float* __restrict__ Wv, const float* __restrict__ bv)
{
    const int h = blockIdx.x;
    const int b = blockIdx.y;
    const int t = threadIdx.x;
    const int p = b * NHEADS + h;

    float* sW   = smem;                 // 128*64
    float* sK2  = sW  + KDIM * HD;      // 257*68
    float* sGV2 = sK2 + NK * ROWP;      // 257*68

    const float* n1b    = node1 + (size_t)b * KDIM * 256;
    const float* n2b    = node2 + (size_t)b * KDIM * 256;
    const float* pooled = seq   + (size_t)b * 4096 * 768;

    // ======== Phase V (Wv in smem): gelu(v2)->sGV2, gelu(v1)->g_v1 ========
    for (int i = t; i < KDIM * HD; i += 256)
        sW[i] = Wv[(i >> 6) * 256 + h * HD + (i & 63)];
    __syncthreads();
    {
        ull acc2[32];
        proj_row(n2b, sW, bv + h * HD, t, acc2);
        float4* dst = (float4*)&sGV2[t * ROWP];
        #pragma unroll
        for (int i = 0; i < 16; i++) {
            float2 a0 = unpack2(acc2[2*i]), a1 = unpack2(acc2[2*i+1]);
            float4 r;
            r.x = gelu_exact(a0.x); r.y = gelu_exact(a0.y);
            r.z = gelu_exact(a1.x); r.w = gelu_exact(a1.y);
            dst[i] = r;
        }
        if (t < HD) {   // V2 extra row from pooled[:128]
            float a = bv[h * HD + t];
            #pragma unroll 4
            for (int k = 0; k < KDIM; k++) a = fmaf(pooled[k], sW[k * HD + t], a);
            sGV2[256 * ROWP + t] = gelu_exact(a);
        }
    }
    {   // V1 (same weights): gelu, park in global scratch
        ull acc2[32];
        proj_row(n1b, sW, bv + h * HD, t, acc2);
        float4* dst = (float4*)&g_v1[(size_t)p * NQ * HD + t * HD];
        #pragma unroll
        for (int i = 0; i < 16; i++) {
            float2 a0 = unpack2(acc2[2*i]), a1 = unpack2(acc2[2*i+1]);
            float4 r;
            r.x = gelu_exact(a0.x); r.y = gelu_exact(a0.y);
            r.z = gelu_exact(a1.x); r.w = gelu_exact(a1.y);
            dst[i] = r;
        }
    }
    __syncthreads();

    // ======== Phase K2 -> sK2 ========
    for (int i = t; i < KDIM * HD; i += 256)
        sW[i] = Wk[(i >> 6) * 256 + h * HD + (i & 63)];
    __syncthreads();
    {
        ull acc2[32];
        proj_row(n2b, sW, bk + h * HD, t, acc2);
        float4* dst = (float4*)&sK2[t * ROWP];
        #pragma unroll
        for (int i = 0; i < 16; i++) {
            float2 a0 = unpack2(acc2[2*i]), a1 = unpack2(acc2[2*i+1]);
            dst[i] = make_float4(a0.x, a0.y, a1.x, a1.y);
        }
        if (t < HD) {
            float a = bk[h * HD + t];
            #pragma unroll 4
            for (int k = 0; k < KDIM; k++) a = fmaf(pooled[k], sW[k * HD + t], a);
            sK2[256 * ROWP + t] = a;
        }
    }
    __syncthreads();

    // ======== Phase Q (registers, pre-scaled by 1/8) ========
    for (int i = t; i < KDIM * HD; i += 256)
        sW[i] = Wq[(i >> 6) * 256 + h * HD + (i & 63)];
    __syncthreads();
    ull q2[32];
    proj_row(n1b, sW, bq + h * HD, t, q2);
    {
        ull sc = pack2(0.125f, 0.125f);
        #pragma unroll
        for (int i = 0; i < 32; i++) q2[i] = mul2(q2[i], sc);
    }

    // ======== Attention: online softmax over 257 keys ========
    ull ctx2[32];
    float m, l;
    {
        const ulonglong2* kr = (const ulonglong2*)&sK2[0];
        ull sa = pack2(0.f, 0.f), sb = sa, sc_ = sa, sd = sa;
        #pragma unroll
        for (int i = 0; i < 8; i++) {
            ulonglong2 ka = kr[2*i], kb = kr[2*i+1];
            sa  = ffma2(q2[4*i],   ka.x, sa);
            sb  = ffma2(q2[4*i+1], ka.y, sb);
            sc_ = ffma2(q2[4*i+2], kb.x, sc_);
            sd  = ffma2(q2[4*i+3], kb.y, sd);
        }
        float2 fa = unpack2(sa), fb = unpack2(sb), fc_ = unpack2(sc_), fd = unpack2(sd);
        m = ((fa.x + fa.y) + (fb.x + fb.y)) + ((fc_.x + fc_.y) + (fd.x + fd.y));
        l = 1.f;
        const ulonglong2* vr = (const ulonglong2*)&sGV2[0];
        #pragma unroll
        for (int i = 0; i < 16; i++) { ulonglong2 v = vr[i]; ctx2[2*i] = v.x; ctx2[2*i+1] = v.y; }
    }
    for (int j = 1; j < NK; j++) {
        const ulonglong2* kr = (const ulonglong2*)&sK2[j * ROWP];
        ull sa = pack2(0.f, 0.f), sb = sa, sc_ = sa, sd = sa;
        #pragma unroll
        for (int i = 0; i < 8; i++) {
            ulonglong2 ka = kr[2*i], kb = kr[2*i+1];
            sa  = ffma2(q2[4*i],   ka.x, sa);
            sb  = ffma2(q2[4*i+1], ka.y, sb);
            sc_ = ffma2(q2[4*i+2], kb.x, sc_);
            sd  = ffma2(q2[4*i+3], kb.y, sd);
        }
        float2 fa = unpack2(sa), fb = unpack2(sb), fc_ = unpack2(sc_), fd = unpack2(sd);
        float s = ((fa.x + fa.y) + (fb.x + fb.y)) + ((fc_.x + fc_.y) + (fd.x + fd.y));
        const ulonglong2* vr = (const ulonglong2*)&sGV2[j * ROWP];
        if (s <= m) {
            float pexp = __expf(s - m);
            l += pexp;
            ull p2 = pack2(pexp, pexp);
            #pragma unroll
            for (int i = 0; i < 16; i++) {
                ulonglong2 v = vr[i];
                ctx2[2*i]   = ffma2(p2, v.x, ctx2[2*i]);
                ctx2[2*i+1] = ffma2(p2, v.y, ctx2[2*i+1]);
            }
        } else {
            float c = __expf(m - s);
            l = fmaf(l, c, 1.f);
            ull c2 = pack2(c, c);
            #pragma unroll
            for (int i = 0; i < 16; i++) {
                ulonglong2 v = vr[i];
                ctx2[2*i]   = ffma2(ctx2[2*i],   c2, v.x);
                ctx2[2*i+1] = ffma2(ctx2[2*i+1], c2, v.y);
            }
            m = s;
        }
    }
    const float inv_l = 1.f / l;

    // ======== Combine with parked gelu(v1) -> sK2 rows ========
    __syncthreads();   // everyone done reading sK2/sGV2
    {
        const float4* src = (const float4*)&g_v1[(size_t)p * NQ * HD + t * HD];
        float4* dst = (float4*)&sK2[t * ROWP];
        #pragma unroll
        for (int i = 0; i < 16; i++) {
            float4 v = src[i];
            float2 c0 = unpack2(ctx2[2*i]), c1 = unpack2(ctx2[2*i+1]);
            float4 r;
            r.x = fmaf(c0.x, inv_l, v.x);
            r.y = fmaf(c0.y, inv_l, v.y);
            r.z = fmaf(c1.x, inv_l, v.z);
            r.w = fmaf(c1.y, inv_l, v.w);
            dst[i] = r;
        }
    }
    __syncthreads();

    // ======== Max over 256 query rows (4-way split) ========
    {
        int o = t & 63, seg = t >> 6;
        float mx = -1e30f;
        #pragma unroll 8
        for (int n = seg * 64; n < seg * 64 + 64; n++)
            mx = fmaxf(mx, sK2[n * ROWP + o]);
        sGV2[seg * 64 + o] = mx;
    }
    __syncthreads();
    if (t < HD) {
        float mx = fmaxf(fmaxf(sGV2[t], sGV2[64 + t]),
                         fmaxf(sGV2[128 + t], sGV2[192 + t]));
        g_maxpool[p * HD + t] = mx;
    }
}

// ---------------------------------------------------------------------------
// Head pipeline (4 wide kernels)
// ---------------------------------------------------------------------------
__device__ __forceinline__ float block_sum(float v, float* red, int t) {
    __syncthreads();
    #pragma unroll
    for (int off = 16; off; off >>= 1) v += __shfl_xor_sync(0xffffffffu, v, off);
    if ((t & 31) == 0) red[t >> 5] = v;
    __syncthreads();
    if (t < 8) {
        v = red[t];
        #pragma unroll
        for (int off = 4; off; off >>= 1) v += __shfl_xor_sync(0xffu, v, off);
        if (t == 0) red[0] = v;
    }
    __syncthreads();
    return red[0];
}

// 2a: Wo proj + layernorm -> g_emb  (grid 32)
__global__ __launch_bounds__(256)
void emb_ln_kernel(
    const float* __restrict__ seq,
    const float* __restrict__ Wo,   const float* __restrict__ bo,
    const float* __restrict__ ln_g, const float* __restrict__ ln_b)
{
    __shared__ float mp_s[256];
    __shared__ float emb[832];
    __shared__ float red[32];
    __shared__ float wo_part[4][64];

    const int b = blockIdx.x;
    const int t = threadIdx.x;

    mp_s[t] = g_maxpool[b * 256 + t];
    for (int i = t; i < 768; i += 256)
        emb[i] = seq[(size_t)b * 4096 * 768 + i];
    __syncthreads();

    {
        int o = t & 63, seg = t >> 6;
        float a = 0.f;
        #pragma unroll 8
        for (int k = seg * 64; k < seg * 64 + 64; k++)
            a = fmaf(mp_s[k], Wo[k * 64 + o], a);
        wo_part[seg][o] = a;
    }
    __syncthreads();
    if (t < 64)
        emb[768 + t] = wo_part[0][t] + wo_part[1][t] + wo_part[2][t] + wo_part[3][t] + bo[t];
    __syncthreads();

    float s = 0.f;
    for (int i = t; i < 832; i += 256) s += emb[i];
    float mu = block_sum(s, red, t) * (1.0f / 832.0f);
    float vs = 0.f;
    for (int i = t; i < 832; i += 256) { float d = emb[i] - mu; vs += d * d; }
    float var = block_sum(vs, red, t) * (1.0f / 832.0f);
    float inv_std = rsqrtf(var + 1e-5f);
    for (int i = t; i < 832; i += 256)
        g_emb[b * 832 + i] = (emb[i] - mu) * inv_std * ln_g[i] + ln_b[i];
}

// 2b: fc1 + gelu -> g_h1  (grid 16 x 32; 32-col tile, 8-way k-split)
__global__ __launch_bounds__(256)
void fc1_kernel(const float* __restrict__ fc1_w, const float* __restrict__ fc1_b)
{
    __shared__ float es[832];
    __shared__ float part[8][32];

    const int tile = blockIdx.x;
    const int b    = blockIdx.y;
    const int t    = threadIdx.x;

    for (int i = t; i < 832; i += 256) es[i] = g_emb[b * 832 + i];
    __syncthreads();

    const int col  = t & 31;
    const int seg  = t >> 5;           // 0..7, each owns 104 k's
    const int gcol = tile * 32 + col;
    const float* w = fc1_w + gcol;

    float a = 0.f;
    const int k0 = seg * 104;
    #pragma unroll 8
    for (int k = k0; k < k0 + 104; k++)
        a = fmaf(es[k], w[(size_t)k * 512], a);
    part[seg][col] = a;
    __syncthreads();

    if (t < 32) {
        float sum = part[0][t] + part[1][t] + part[2][t] + part[3][t]
                  + part[4][t] + part[5][t] + part[6][t] + part[7][t];
        int gc = tile * 32 + t;
        g_h1[b * 512 + gc] = gelu_exact(sum + fc1_b[gc]);
    }
}

// 2c: fc2 partials (k-split 2) -> g_h2p  (grid 2 x 32)
__global__ __launch_bounds__(256)
void fc2_kernel(const float* __restrict__ fc2_w)
{
    __shared__ float hs[256];
    const int seg = blockIdx.x;        // 0 or 1: k in [seg*256, seg*256+256)
    const int b   = blockIdx.y;
    const int t   = threadIdx.x;

    hs[t] = g_h1[b * 512 + seg * 256 + t];
    __syncthreads();

    if (t < 200) {
        const float* w = fc2_w + (size_t)(seg * 256) * 200 + t;
        float a0 = 0.f, a1 = 0.f;
        #pragma unroll 8
        for (int k = 0; k < 256; k += 2) {
            a0 = fmaf(hs[k],     w[(size_t)k * 200],       a0);
            a1 = fmaf(hs[k + 1], w[(size_t)(k + 1) * 200], a1);
        }
        g_h2p[(seg * 32 + b) * 200 + t] = a0 + a1;
    }
}

// 2d: combine fc2 partials + gelu, fc3 -> out  (grid 32)
__global__ __launch_bounds__(256)
void fc3_kernel(const float* __restrict__ fc2_b,
                const float* __restrict__ fc3_w, const float* __restrict__ fc3_b,
                float* __restrict__ out)
{
    __shared__ float h2[200];
    const int b = blockIdx.x;
    const int t = threadIdx.x;

    if (t < 200)
        h2[t] = gelu_exact(g_h2p[b * 200 + t] + g_h2p[(32 + b) * 200 + t] + fc2_b[t]);
    __syncthreads();

    if (t < 64) {
        int o = t >> 5, lane = t & 31;
        float a = 0.f;
        #pragma unroll
        for (int k = lane; k < 200; k += 32) a = fmaf(h2[k], fc3_w[k * 2 + o], a);
        #pragma unroll
        for (int off = 16; off; off >>= 1) a += __shfl_xor_sync(0xffffffffu, a, off);
        if (lane == 0) out[b * 2 + o] = a + fc3_b[o];
    }
}

// ---------------------------------------------------------------------------
extern "C" void kernel_launch(void* const* d_in, const int* in_sizes, int n_in,
                              void* d_out, int out_size)
{
    const float* seq    = (const float*)d_in[0];
    const float* node1  = (const float*)d_in[1];
    const float* node2  = (const float*)d_in[2];
    const float* Wq     = (const float*)d_in[3];
    const float* bq     = (const float*)d_in[4];
    const float* Wk     = (const float*)d_in[5];
    const float* bk     = (const float*)d_in[6];
    const float* Wv     = (const float*)d_in[7];
    const float* bv     = (const float*)d_in[8];
    const float* Wo     = (const float*)d_in[9];
    const float* bo     = (const float*)d_in[10];
    const float* ln_g   = (const float*)d_in[11];
    const float* ln_b   = (const float*)d_in[12];
    const float* fc1_w  = (const float*)d_in[13];
    const float* fc1_b  = (const float*)d_in[14];
    const float* fc2_w  = (const float*)d_in[15];
    const float* fc2_b  = (const float*)d_in[16];
    const float* fc3_w  = (const float*)d_in[17];
    const float* fc3_b  = (const float*)d_in[18];

    const size_t smem_bytes = (size_t)(KDIM * HD + 2 * NK * ROWP) * sizeof(float);
    cudaFuncSetAttribute(attn_fused_kernel,
                         cudaFuncAttributeMaxDynamicSharedMemorySize,
                         (int)smem_bytes);

    attn_fused_kernel<<<dim3(NHEADS, 32), 256, smem_bytes>>>(
        seq, node1, node2, Wq, bq, Wk, bk, Wv, bv);

    emb_ln_kernel<<<32, 256>>>(seq, Wo, bo, ln_g, ln_b);
    fc1_kernel<<<dim3(16, 32), 256>>>(fc1_w, fc1_b);
    fc2_kernel<<<dim3(2, 32), 256>>>(fc2_w);
    fc3_kernel<<<32, 256>>>(fc2_b, fc3_w, fc3_b, (float*)d_out);
}